// round 1
// baseline (speedup 1.0000x reference)
#include <cuda_runtime.h>

// CML score kernel: out[u, i] = -||U[ids[u]] - I[i]||^2
//                             = 2 * (U[ids[u]] . I[i]) - ||U||^2 - ||I||^2
// GEMM M=256, N=500000, K=64 fused with norm epilogue.
// Packed f32x2 FMA (fma.rn.f32x2) for 2x fp32 FMA throughput on sm_103a.

constexpr int DIM     = 64;
constexpr int BM      = 128;   // users per block (grid.y = 2 covers 256)
constexpr int BN      = 128;   // items per block
constexpr int TM      = 8;     // users per thread
constexpr int TN      = 4;     // items per thread
constexpr int THREADS = 512;   // (BM/TM)*(BN/TN) = 16*32

__device__ __forceinline__ unsigned long long pk2(float lo, float hi) {
    unsigned long long r;
    asm("mov.b64 %0, {%1, %2};" : "=l"(r) : "f"(lo), "f"(hi));
    return r;
}
__device__ __forceinline__ void fma2(unsigned long long& d,
                                     unsigned long long a,
                                     unsigned long long b) {
    asm("fma.rn.f32x2 %0, %1, %2, %0;" : "+l"(d) : "l"(a), "l"(b));
}
__device__ __forceinline__ float2 upk2(unsigned long long v) {
    float2 f;
    asm("mov.b64 {%0, %1}, %2;" : "=f"(f.x), "=f"(f.y) : "l"(v));
    return f;
}

__global__ __launch_bounds__(THREADS)
void cml_main(const int* __restrict__ ids,
              const float* __restrict__ U,
              const float* __restrict__ I,
              float* __restrict__ out,
              int nItems)
{
    extern __shared__ float smem[];
    float* As  = smem;               // [DIM][BM] K-major, 16B-group swizzled
    float* Bs  = smem + DIM * BM;    // [DIM][BN] K-major, 16B-group swizzled
    float* usq = Bs + DIM * BN;      // [BM]
    float* isq = usq + BM;           // [BN]

    const int tid      = threadIdx.x;
    const int itemBase = blockIdx.x * BN;
    const int userBase = blockIdx.y * BM;

    // ---- Load tiles (transpose into K-major with swizzle) -----------------
    // Swizzle: element (k, c) lives at column group ((c>>2) ^ (k>>2)), offset c&3.
    // Writer: thread owns float4 chunk d4 (k = 4*d4..4*d4+3 -> k>>2 == d4).
    {
        const int d4 = tid & 15;       // which float4 of the 64-float row
        const int r0 = tid >> 4;       // row 0..31, step 32
        #pragma unroll
        for (int rr = 0; rr < 4; rr++) {
            const int r   = r0 + rr * 32;
            const int col = (((r >> 2) ^ d4) << 2) + (r & 3);

            // A: gathered user row, row r of this block's 128 users
            const int uid = ids[userBase + r];
            const float4 va = *(const float4*)(U + (size_t)uid * DIM + d4 * 4);
            As[(4 * d4 + 0) * BM + col] = va.x;
            As[(4 * d4 + 1) * BM + col] = va.y;
            As[(4 * d4 + 2) * BM + col] = va.z;
            As[(4 * d4 + 3) * BM + col] = va.w;

            // B: item row (zero-pad past nItems; those outputs are never stored)
            const int item = itemBase + r;
            float4 vb = make_float4(0.f, 0.f, 0.f, 0.f);
            if (item < nItems)
                vb = *(const float4*)(I + (size_t)item * DIM + d4 * 4);
            Bs[(4 * d4 + 0) * BN + col] = vb.x;
            Bs[(4 * d4 + 1) * BN + col] = vb.y;
            Bs[(4 * d4 + 2) * BN + col] = vb.z;
            Bs[(4 * d4 + 3) * BN + col] = vb.w;
        }
    }
    __syncthreads();

    // ---- Squared norms from the SMEM tiles (warps 0-3: users, 4-7: items) --
    if (tid < 256) {
        const int   m    = tid & 127;
        const float* base = (tid < 128) ? As : Bs;
        float s = 0.f;
        #pragma unroll
        for (int k = 0; k < DIM; k++) {
            const float v = base[k * BM + ((((m >> 2) ^ (k >> 2)) << 2) + (m & 3))];
            s = fmaf(v, v, s);
        }
        if (tid < 128) usq[m] = s; else isq[m] = s;
    }
    __syncthreads();

    // ---- Main K loop: packed f32x2 FMA, accumulators paired over users ----
    const int warp = tid >> 5;
    const int lane = tid & 31;
    const int tm   = warp * TM;    // user offset within tile
    const int tn   = lane * TN;    // item offset within tile
    const int g0   = tm >> 2;      // = warp*2: first 4-user group

    unsigned long long acc[4][4];
    #pragma unroll
    for (int j = 0; j < 4; j++)
        #pragma unroll
        for (int n = 0; n < 4; n++) acc[j][n] = 0ULL;

    #pragma unroll 8
    for (int k = 0; k < DIM; k++) {
        const int x = k >> 2;
        // a: 8 users (two 16B groups), warp-uniform address -> LDS broadcast
        const float4 a0 = *(const float4*)&As[k * BM + (( g0      ^ x) << 2)];
        const float4 a1 = *(const float4*)&As[k * BM + (((g0 + 1) ^ x) << 2)];
        // b: 4 items, lanes hit distinct 16B groups -> conflict-free LDS.128
        const float4 b  = *(const float4*)&Bs[k * BN + ((lane ^ x) << 2)];

        unsigned long long a2[4] = { pk2(a0.x, a0.y), pk2(a0.z, a0.w),
                                     pk2(a1.x, a1.y), pk2(a1.z, a1.w) };
        unsigned long long b2[4] = { pk2(b.x, b.x), pk2(b.y, b.y),
                                     pk2(b.z, b.z), pk2(b.w, b.w) };
        #pragma unroll
        for (int j = 0; j < 4; j++)
            #pragma unroll
            for (int n = 0; n < 4; n++)
                fma2(acc[j][n], a2[j], b2[n]);
    }

    // ---- Epilogue: score = 2*cross - usq - isq, coalesced STG.128 ----------
    // Last tile: 500000 % 4 == 0, so a thread's 4 items are all-valid or all-invalid.
    if (itemBase + tn >= nItems) return;

    const float i0 = isq[tn], i1 = isq[tn + 1], i2 = isq[tn + 2], i3 = isq[tn + 3];
    #pragma unroll
    for (int j = 0; j < 4; j++) {
        const float2 c0 = upk2(acc[j][0]);
        const float2 c1 = upk2(acc[j][1]);
        const float2 c2 = upk2(acc[j][2]);
        const float2 c3 = upk2(acc[j][3]);
        const int   mlo = tm + 2 * j;
        const float ul  = usq[mlo];
        const float uh  = usq[mlo + 1];

        float4 vlo, vhi;
        vlo.x = fmaf(2.f, c0.x, -(ul + i0));
        vlo.y = fmaf(2.f, c1.x, -(ul + i1));
        vlo.z = fmaf(2.f, c2.x, -(ul + i2));
        vlo.w = fmaf(2.f, c3.x, -(ul + i3));
        vhi.x = fmaf(2.f, c0.y, -(uh + i0));
        vhi.y = fmaf(2.f, c1.y, -(uh + i1));
        vhi.z = fmaf(2.f, c2.y, -(uh + i2));
        vhi.w = fmaf(2.f, c3.y, -(uh + i3));

        const size_t rowlo = (size_t)(userBase + mlo) * (size_t)nItems
                           + (size_t)(itemBase + tn);
        *(float4*)(out + rowlo)              = vlo;
        *(float4*)(out + rowlo + nItems)     = vhi;
    }
}

extern "C" void kernel_launch(void* const* d_in, const int* in_sizes, int n_in,
                              void* d_out, int out_size) {
    const int*   ids = (const int*)d_in[0];     // [256] int32
    const float* U   = (const float*)d_in[1];   // [100000, 64] fp32
    const float* I   = (const float*)d_in[2];   // [500000, 64] fp32
    float*       out = (float*)d_out;           // [256, 500000] fp32

    const int nScore = in_sizes[0];
    const int nItems = in_sizes[2] / DIM;

    const size_t smemBytes = (size_t)(2 * DIM * BM + BM + BN) * sizeof(float); // 66560
    cudaFuncSetAttribute(cml_main, cudaFuncAttributeMaxDynamicSharedMemorySize,
                         (int)smemBytes);

    dim3 grid((nItems + BN - 1) / BN, nScore / BM);
    cml_main<<<grid, THREADS, smemBytes>>>(ids, U, I, out, nItems);
}

// round 3
// speedup vs baseline: 1.1508x; 1.1508x over previous
#include <cuda_runtime.h>
#include <cstdint>

// CML scores: out[u,i] = 2*dot(U[ids[u]], I[i]) - ||u||^2 - ||i||^2
// GEMM M=256 x N=500000 x K=64 via mma.sync.m16n8k8 tf32 (fp32 accum).
// Per CTA: 256x128 tile, A resident in frag-ready SMEM, B double-buffered.
// Norms exact fp32. Epilogue: direct STG.64 from C fragments (full sectors).

#define THREADS 512
#define SM_AFRAG   0          // 8 ksteps x 16 mtiles x 32 groups x 16B = 64KB
#define SM_BFRAG   65536      // 2 bufs x (8 ksteps x 8 npairs x 32 x 16B) = 64KB
#define SM_USQ     131072     // 256 floats
#define SM_ISQ     132096     // 2 x 128 floats
#define SM_TOTAL   133120

__device__ __forceinline__ uint32_t cvt_tf32(float x) {
    uint32_t r;
    asm("cvt.rna.tf32.f32 %0, %1;" : "=r"(r) : "f"(x));
    return r;
}
__device__ __forceinline__ void mma_tf32(float* c, const uint32_t* a,
                                         uint32_t b0, uint32_t b1) {
    asm volatile(
        "mma.sync.aligned.m16n8k8.row.col.f32.tf32.tf32.f32 "
        "{%0,%1,%2,%3}, {%4,%5,%6,%7}, {%8,%9}, {%0,%1,%2,%3};"
        : "+f"(c[0]), "+f"(c[1]), "+f"(c[2]), "+f"(c[3])
        : "r"(a[0]), "r"(a[1]), "r"(a[2]), "r"(a[3]), "r"(b0), "r"(b1));
}

// Load next B tile's data into registers (16 floats/thread). Thread mapping:
// l2 = tid>>3: np = l2>>3 (item pair-of-ntiles), cc = l2&7 (col in ntile);
// q = tid&7 = kstep; items (np*16+cc) and (+8), k in [q*8, q*8+8).
__device__ __forceinline__ void loadB(const float* __restrict__ I, int tile,
                                      int nItems, int tid,
                                      float* f0, float* f1) {
    const int l2 = tid >> 3, q = tid & 7;
    const int np = l2 >> 3, cc = l2 & 7;
    const int it0 = tile * 128 + np * 16 + cc;
    const int it1 = it0 + 8;
    float4 a0 = make_float4(0.f, 0.f, 0.f, 0.f), a1 = a0, b0 = a0, b1 = a0;
    if (it0 < nItems) {
        const float* p = I + (size_t)it0 * 64 + q * 8;
        a0 = *(const float4*)p; a1 = *(const float4*)(p + 4);
    }
    if (it1 < nItems) {
        const float* p = I + (size_t)it1 * 64 + q * 8;
        b0 = *(const float4*)p; b1 = *(const float4*)(p + 4);
    }
    f0[0] = a0.x; f0[1] = a0.y; f0[2] = a0.z; f0[3] = a0.w;
    f0[4] = a1.x; f0[5] = a1.y; f0[6] = a1.z; f0[7] = a1.w;
    f1[0] = b0.x; f1[1] = b0.y; f1[2] = b0.z; f1[3] = b0.w;
    f1[4] = b1.x; f1[5] = b1.y; f1[6] = b1.z; f1[7] = b1.w;
}

// Reduce norms, write isq, convert to tf32, scatter into frag layout.
// Group-index XOR q makes the 4 STS.128 per thread bank-conflict-free.
__device__ __forceinline__ void storeB(char* smem, float* isqb, int tid,
                                       const float* f0, const float* f1,
                                       int buf) {
    const int l2 = tid >> 3, q = tid & 7;
    const int np = l2 >> 3, cc = l2 & 7;

    float s0 = 0.f, s1 = 0.f;
    #pragma unroll
    for (int m = 0; m < 8; m++) { s0 = fmaf(f0[m], f0[m], s0);
                                  s1 = fmaf(f1[m], f1[m], s1); }
    s0 += __shfl_xor_sync(0xffffffffu, s0, 1);
    s0 += __shfl_xor_sync(0xffffffffu, s0, 2);
    s0 += __shfl_xor_sync(0xffffffffu, s0, 4);
    s1 += __shfl_xor_sync(0xffffffffu, s1, 1);
    s1 += __shfl_xor_sync(0xffffffffu, s1, 2);
    s1 += __shfl_xor_sync(0xffffffffu, s1, 4);
    if (q == 0) { isqb[np * 16 + cc] = s0; isqb[np * 16 + cc + 8] = s1; }

    char* base = smem + SM_BFRAG + buf * 32768 + (q * 8 + np) * 512;
    #pragma unroll
    for (int m = 0; m < 4; m++) {
        uint4 v;
        v.x = cvt_tf32(f0[m]);     v.y = cvt_tf32(f0[m + 4]);
        v.z = cvt_tf32(f1[m]);     v.w = cvt_tf32(f1[m + 4]);
        *(uint4*)(base + (((cc * 4 + m) ^ q) << 4)) = v;
    }
}

__global__ __launch_bounds__(THREADS, 1)
void cml_mma(const int* __restrict__ ids,
             const float* __restrict__ U,
             const float* __restrict__ I,
             float* __restrict__ out,
             int nItems)
{
    extern __shared__ char smem[];
    float* usq = (float*)(smem + SM_USQ);
    float* isq = (float*)(smem + SM_ISQ);   // [2][128]

    const int tid  = threadIdx.x;
    const int lane = tid & 31;
    const int wm   = (tid >> 5) >> 1;       // warp M index 0..7 (32 rows each)
    const int wn   = (tid >> 5) & 1;        // warp N index 0..1 (64 cols each)

    // ---- Prologue: A (256 users) -> tf32 frag layout + usq ----------------
    {
        const int row = tid >> 1, h = tid & 1;
        const int uid = ids[row];
        const float* up = U + (size_t)uid * 64 + h * 32;
        float av[32];
        #pragma unroll
        for (int w = 0; w < 8; w++) {
            const float4 t = ((const float4*)up)[w];
            av[4*w] = t.x; av[4*w+1] = t.y; av[4*w+2] = t.z; av[4*w+3] = t.w;
        }
        float s = 0.f;
        #pragma unroll
        for (int j = 0; j < 32; j++) s = fmaf(av[j], av[j], s);
        s += __shfl_xor_sync(0xffffffffu, s, 1);   // pair (h=0,1) same row
        if (h == 0) usq[row] = s;

        const int mt = row >> 4, r = row & 15;
        #pragma unroll
        for (int j = 0; j < 32; j++) {
            const int k = h * 32 + j, ks = k >> 3, c = k & 7;
            const int la   = (r & 7) * 4 + (c & 3);
            const int slot = ((r >> 3) & 1) + ((c >> 2) << 1);
            *(uint32_t*)(smem + (ks * 16 + mt) * 512 + ((la ^ ks) << 4)
                         + slot * 4) = cvt_tf32(av[j]);
        }
    }

    // ---- Tile loop over items (double-buffered B) -------------------------
    const int NT = (nItems + 127) >> 7;
    float f0[8], f1[8];
    int tile = blockIdx.x;
    loadB(I, tile, nItems, tid, f0, f1);
    int buf = 0;

    for (; tile < NT; tile += gridDim.x) {
        storeB(smem, isq + buf * 128, tid, f0, f1, buf);
        __syncthreads();   // B frags + isq (and prologue A on first iter) ready

        const int nextTile = tile + gridDim.x;
        if (nextTile < NT) loadB(I, nextTile, nItems, tid, f0, f1); // overlaps MMA

        // ---- MMA: 2 mtiles x 8 ntiles x 8 ksteps --------------------------
        float acc[2][8][4];
        #pragma unroll
        for (int a = 0; a < 2; a++)
            #pragma unroll
            for (int b = 0; b < 8; b++)
                #pragma unroll
                for (int cdx = 0; cdx < 4; cdx++) acc[a][b][cdx] = 0.f;

        const char* Bf = smem + SM_BFRAG + buf * 32768;
        #pragma unroll
        for (int ks = 0; ks < 8; ks++) {
            const int g = (lane ^ ks) << 4;
            uint4 a0 = *(const uint4*)(smem + (ks * 16 + wm * 2    ) * 512 + g);
            uint4 a1 = *(const uint4*)(smem + (ks * 16 + wm * 2 + 1) * 512 + g);
            #pragma unroll
            for (int p = 0; p < 4; p++) {
                const uint4 b = *(const uint4*)(Bf + (ks * 8 + wn * 4 + p) * 512 + g);
                mma_tf32(acc[0][2*p    ], (const uint32_t*)&a0, b.x, b.y);
                mma_tf32(acc[1][2*p    ], (const uint32_t*)&a1, b.x, b.y);
                mma_tf32(acc[0][2*p + 1], (const uint32_t*)&a0, b.z, b.w);
                mma_tf32(acc[1][2*p + 1], (const uint32_t*)&a1, b.z, b.w);
            }
        }

        // ---- Epilogue: score = 2c - usq - isq, STG.64 full sectors --------
        const float* isqb = isq + buf * 128;
        #pragma unroll
        for (int mt = 0; mt < 2; mt++) {
            const int rg = wm * 32 + mt * 16 + (lane >> 2);
            const float u0 = usq[rg], u1 = usq[rg + 8];
            const size_t r0off = (size_t)rg * (size_t)nItems;
            const size_t r1off = r0off + (size_t)8 * (size_t)nItems;
            #pragma unroll
            for (int p = 0; p < 4; p++) {
                #pragma unroll
                for (int e = 0; e < 2; e++) {
                    const int cl  = (wn * 4 + p) * 16 + e * 8 + (lane & 3) * 2;
                    const int col = tile * 128 + cl;
                    if (col < nItems) {
                        const float2 iq = *(const float2*)&isqb[cl];
                        const float* c  = acc[mt][2 * p + e];
                        float2 v0, v1;
                        v0.x = fmaf(2.f, c[0], -(u0 + iq.x));
                        v0.y = fmaf(2.f, c[1], -(u0 + iq.y));
                        v1.x = fmaf(2.f, c[2], -(u1 + iq.x));
                        v1.y = fmaf(2.f, c[3], -(u1 + iq.y));
                        *(float2*)(out + r0off + col) = v0;
                        *(float2*)(out + r1off + col) = v1;
                    }
                }
            }
        }

        buf ^= 1;
    }
}

extern "C" void kernel_launch(void* const* d_in, const int* in_sizes, int n_in,
                              void* d_out, int out_size) {
    const int*   ids = (const int*)d_in[0];     // [256]
    const float* U   = (const float*)d_in[1];   // [100000, 64]
    const float* I   = (const float*)d_in[2];   // [500000, 64]
    float*       out = (float*)d_out;           // [256, 500000]

    const int nItems = in_sizes[2] / 64;

    cudaFuncSetAttribute(cml_mma, cudaFuncAttributeMaxDynamicSharedMemorySize,
                         SM_TOTAL);
    cml_mma<<<592, THREADS, SM_TOTAL>>>(ids, U, I, out, nItems);
}

// round 5
// speedup vs baseline: 2.2360x; 1.9431x over previous
#include <cuda_runtime.h>
#include <cstdint>

// CML scores: out[u,i] = 2*dot(U[ids[u]], I[i]) - ||u||^2 - ||i||^2
// GEMM M=256 x N=500000 x K=64, mma.sync.m16n8k8 tf32 (fp32 accum).
// CTA: 256 threads, tile 256x64, A resident (64KB frag SMEM), B double-
// buffered (2x16KB) with register prefetch. 2 CTAs/SM. Items read once.
// B columns permuted so the epilogue is pure STG.128 full-sector stores.

#define THREADS 256
#define SM_AFRAG   0          // 8 ks x 16 mtiles x 32 groups x 16B = 64KB
#define SM_BFRAG   65536      // 2 bufs x (8 ks x 4 pairs x 512B) = 32KB
#define SM_USQ     98304      // 256 floats
#define SM_ISQ     99328      // 2 x 64 floats
#define SM_TOTAL   99840

__device__ __forceinline__ uint32_t cvt_tf32(float x) {
    uint32_t r;
    asm("cvt.rna.tf32.f32 %0, %1;" : "=r"(r) : "f"(x));
    return r;
}
__device__ __forceinline__ void mma_tf32(float* c, const uint32_t* a,
                                         uint32_t b0, uint32_t b1) {
    asm volatile(
        "mma.sync.aligned.m16n8k8.row.col.f32.tf32.tf32.f32 "
        "{%0,%1,%2,%3}, {%4,%5,%6,%7}, {%8,%9}, {%0,%1,%2,%3};"
        : "+f"(c[0]), "+f"(c[1]), "+f"(c[2]), "+f"(c[3])
        : "r"(a[0]), "r"(a[1]), "r"(a[2]), "r"(a[3]), "r"(b0), "r"(b1));
}

// Column permutation: frag position (ntile n = 2*np+e, fragcol cc) holds
// local column  np*16 + (cc>>1)*4 + e*2 + (cc&1)  -> a thread's 4 C-values
// per (mtile, pair) are 4 consecutive columns => STG.128 epilogue.

// Thread mapping for B: q = tid&7 (kstep), l2 = tid>>3: np = l2>>3 (pair 0..3),
// cc = l2&7. Loads items for (2np, cc) and (2np+1, cc), k in [8q, 8q+8).
__device__ __forceinline__ void loadB(const float* __restrict__ I, int tile,
                                      int nItems, int tid,
                                      float* f0, float* f1) {
    const int q  = tid & 7, l2 = tid >> 3;
    const int np = l2 >> 3, cc = l2 & 7;
    const int c0  = np * 16 + ((cc >> 1) << 2) + (cc & 1);
    const int it0 = tile * 64 + c0;         // e = 0
    const int it1 = it0 + 2;                // e = 1
    float4 a0 = make_float4(0.f, 0.f, 0.f, 0.f), a1 = a0, b0 = a0, b1 = a0;
    if (it0 < nItems) {
        const float* p = I + (size_t)it0 * 64 + q * 8;
        a0 = *(const float4*)p; a1 = *(const float4*)(p + 4);
    }
    if (it1 < nItems) {
        const float* p = I + (size_t)it1 * 64 + q * 8;
        b0 = *(const float4*)p; b1 = *(const float4*)(p + 4);
    }
    f0[0] = a0.x; f0[1] = a0.y; f0[2] = a0.z; f0[3] = a0.w;
    f0[4] = a1.x; f0[5] = a1.y; f0[6] = a1.z; f0[7] = a1.w;
    f1[0] = b0.x; f1[1] = b0.y; f1[2] = b0.z; f1[3] = b0.w;
    f1[4] = b1.x; f1[5] = b1.y; f1[6] = b1.z; f1[7] = b1.w;
}

__device__ __forceinline__ void storeB(char* smem, float* isqb, int tid,
                                       const float* f0, const float* f1,
                                       int buf) {
    const int q  = tid & 7, l2 = tid >> 3;
    const int np = l2 >> 3, cc = l2 & 7;

    float s0 = 0.f, s1 = 0.f;
    #pragma unroll
    for (int m = 0; m < 8; m++) { s0 = fmaf(f0[m], f0[m], s0);
                                  s1 = fmaf(f1[m], f1[m], s1); }
    s0 += __shfl_xor_sync(0xffffffffu, s0, 1);
    s0 += __shfl_xor_sync(0xffffffffu, s0, 2);
    s0 += __shfl_xor_sync(0xffffffffu, s0, 4);
    s1 += __shfl_xor_sync(0xffffffffu, s1, 1);
    s1 += __shfl_xor_sync(0xffffffffu, s1, 2);
    s1 += __shfl_xor_sync(0xffffffffu, s1, 4);
    if (q == 0) {
        const int c0 = np * 16 + ((cc >> 1) << 2) + (cc & 1);
        isqb[c0] = s0; isqb[c0 + 2] = s1;
    }

    char* base = smem + SM_BFRAG + buf * 16384 + (q * 4 + np) * 512;
    #pragma unroll
    for (int m = 0; m < 4; m++) {
        uint4 v;
        v.x = cvt_tf32(f0[m]); v.y = cvt_tf32(f0[m + 4]);
        v.z = cvt_tf32(f1[m]); v.w = cvt_tf32(f1[m + 4]);
        *(uint4*)(base + (((cc * 4 + m) ^ q) << 4)) = v;
    }
}

__global__ __launch_bounds__(THREADS, 2)
void cml_mma(const int* __restrict__ ids,
             const float* __restrict__ U,
             const float* __restrict__ I,
             float* __restrict__ out,
             int nItems)
{
    extern __shared__ char smem[];
    float* usq = (float*)(smem + SM_USQ);
    float* isq = (float*)(smem + SM_ISQ);   // [2][64]

    const int tid  = threadIdx.x;
    const int lane = tid & 31;
    const int wm   = (tid >> 5) >> 1;       // 0..3: 64 user-rows each
    const int wn   = (tid >> 5) & 1;        // 0..1: 32 item-cols each

    // ---- Prologue: A (256 users) -> tf32 frag layout + exact usq ----------
    {
        const int row = tid;
        const int uid = ids[row];
        const float* up = U + (size_t)uid * 64;
        float av[64];
        #pragma unroll
        for (int w = 0; w < 16; w++) {
            const float4 t = ((const float4*)up)[w];
            av[4*w] = t.x; av[4*w+1] = t.y; av[4*w+2] = t.z; av[4*w+3] = t.w;
        }
        float s = 0.f;
        #pragma unroll
        for (int j = 0; j < 64; j++) s = fmaf(av[j], av[j], s);
        usq[row] = s;

        const int mt = row >> 4, r = row & 15;
        #pragma unroll
        for (int j = 0; j < 64; j++) {
            const int ks = j >> 3, c = j & 7;
            const int la   = (r & 7) * 4 + (c & 3);
            const int slot = ((r >> 3) & 1) + ((c >> 2) << 1);
            *(uint32_t*)(smem + (ks * 16 + mt) * 512 + ((la ^ ks) << 4)
                         + slot * 4) = cvt_tf32(av[j]);
        }
    }

    // ---- Tile loop over items (double-buffered B, register prefetch) ------
    const int NT = (nItems + 63) >> 6;
    float f0[8], f1[8];
    int tile = blockIdx.x;
    loadB(I, tile, nItems, tid, f0, f1);
    int buf = 0;

    for (; tile < NT; tile += gridDim.x) {
        storeB(smem, isq + buf * 64, tid, f0, f1, buf);
        __syncthreads();   // B frags + isq (and A on first iter) visible

        const int nextTile = tile + gridDim.x;
        if (nextTile < NT) loadB(I, nextTile, nItems, tid, f0, f1);

        // ---- MMA: 4 mtiles x 4 ntiles x 8 ksteps --------------------------
        float acc[4][4][4];
        #pragma unroll
        for (int a = 0; a < 4; a++)
            #pragma unroll
            for (int b = 0; b < 4; b++)
                #pragma unroll
                for (int cdx = 0; cdx < 4; cdx++) acc[a][b][cdx] = 0.f;

        const char* Bf = smem + SM_BFRAG + buf * 16384;
        #pragma unroll
        for (int ks = 0; ks < 8; ks++) {
            const int g = (lane ^ ks) << 4;
            uint4 a0 = *(const uint4*)(smem + (ks * 16 + wm * 4    ) * 512 + g);
            uint4 a1 = *(const uint4*)(smem + (ks * 16 + wm * 4 + 1) * 512 + g);
            uint4 a2 = *(const uint4*)(smem + (ks * 16 + wm * 4 + 2) * 512 + g);
            uint4 a3 = *(const uint4*)(smem + (ks * 16 + wm * 4 + 3) * 512 + g);
            #pragma unroll
            for (int p = 0; p < 2; p++) {
                const uint4 b = *(const uint4*)(Bf + (ks * 4 + wn * 2 + p) * 512 + g);
                mma_tf32(acc[0][2*p    ], (const uint32_t*)&a0, b.x, b.y);
                mma_tf32(acc[1][2*p    ], (const uint32_t*)&a1, b.x, b.y);
                mma_tf32(acc[2][2*p    ], (const uint32_t*)&a2, b.x, b.y);
                mma_tf32(acc[3][2*p    ], (const uint32_t*)&a3, b.x, b.y);
                mma_tf32(acc[0][2*p + 1], (const uint32_t*)&a0, b.z, b.w);
                mma_tf32(acc[1][2*p + 1], (const uint32_t*)&a1, b.z, b.w);
                mma_tf32(acc[2][2*p + 1], (const uint32_t*)&a2, b.z, b.w);
                mma_tf32(acc[3][2*p + 1], (const uint32_t*)&a3, b.z, b.w);
            }
        }

        // ---- Epilogue: score = 2c - usq - isq, STG.128 full sectors -------
        const float* isqb = isq + buf * 64;
        #pragma unroll
        for (int mt = 0; mt < 4; mt++) {
            const int rg = wm * 64 + mt * 16 + (lane >> 2);
            const float u0 = usq[rg], u1 = usq[rg + 8];
            const size_t r0off = (size_t)rg * (size_t)nItems;
            const size_t r1off = r0off + (size_t)8 * (size_t)nItems;
            #pragma unroll
            for (int p = 0; p < 2; p++) {
                const int cl  = (wn * 2 + p) * 16 + (lane & 3) * 4;
                const int col = tile * 64 + cl;
                if (col < nItems) {
                    const float4 iq = *(const float4*)&isqb[cl];
                    const float* cA = acc[mt][2 * p];
                    const float* cB = acc[mt][2 * p + 1];
                    float4 v0, v1;
                    v0.x = fmaf(2.f, cA[0], -(u0 + iq.x));
                    v0.y = fmaf(2.f, cA[1], -(u0 + iq.y));
                    v0.z = fmaf(2.f, cB[0], -(u0 + iq.z));
                    v0.w = fmaf(2.f, cB[1], -(u0 + iq.w));
                    v1.x = fmaf(2.f, cA[2], -(u1 + iq.x));
                    v1.y = fmaf(2.f, cA[3], -(u1 + iq.y));
                    v1.z = fmaf(2.f, cB[2], -(u1 + iq.z));
                    v1.w = fmaf(2.f, cB[3], -(u1 + iq.w));
                    *(float4*)(out + r0off + col) = v0;
                    *(float4*)(out + r1off + col) = v1;
                }
            }
        }

        buf ^= 1;
    }
}

extern "C" void kernel_launch(void* const* d_in, const int* in_sizes, int n_in,
                              void* d_out, int out_size) {
    const int*   ids = (const int*)d_in[0];     // [256]
    const float* U   = (const float*)d_in[1];   // [100000, 64]
    const float* I   = (const float*)d_in[2];   // [500000, 64]
    float*       out = (float*)d_out;           // [256, 500000]

    const int nItems = in_sizes[2] / 64;

    cudaFuncSetAttribute(cml_mma, cudaFuncAttributeMaxDynamicSharedMemorySize,
                         SM_TOTAL);
    cml_mma<<<296, THREADS, SM_TOTAL>>>(ids, U, I, out, nItems);
}